// round 1
// baseline (speedup 1.0000x reference)
#include <cuda_runtime.h>

// ---------------------------------------------------------------------------
// SMPL fused pipeline.
// Inputs (metadata order):
//  0 beta   (1024,10)      1 theta (1024,72)    2 trans (1024,3)
//  3 v_template (6890,3)   4 shapedirs (10, 20670)
//  5 J_regressor (6890,24) 6 posedirs (207, 20670)
//  7 joint_regressor (6890,19)                  8 weights (6890,24)
// Output: joints (1024,19,3) float32
// ---------------------------------------------------------------------------

namespace smpl {

constexpr int V    = 6890;
constexpr int NB   = 10;
constexpr int NJ   = 24;
constexpr int NPF  = 207;
constexpr int NK   = 19;
constexpr int B    = 1024;

// GEMM1: C[M1 x N1] = G^T[M1 x VP] @ E[VP x N1]
constexpr int VP   = 6912;            // V padded to mult of 16
constexpr int M1   = 512;             // 456 (k*24+j) + 24 (J_regressor rows) + pad
constexpr int N1   = 704;             // 621 posedirs + 30 shapedirs + 3 template + 1 ones + pad
constexpr int SPLITK = 8;             // VP/8 = 864 = 54*16
// GEMM2: P[B x N2] = A2[B x KQ] @ CT[KQ x N2]
constexpr int KQ   = 224;             // 1 + 10 + 207 = 218, padded
constexpr int N2   = 1408;            // 456*3 = 1368, padded

__device__ __align__(256) float g_E  [VP * N1];          // ~19.5 MB
__device__ __align__(256) float g_G  [VP * M1];          // ~14.2 MB
__device__ __align__(256) float g_Cp [SPLITK * M1 * N1]; // ~11.5 MB split-K partials
__device__ __align__(256) float g_CT [KQ * N2];          // 1.26 MB
__device__ __align__(256) float g_S  [456];              // S[k*24+j] = sum_v jr*w
__device__ __align__(256) float g_JT [24 * 33];          // J-regression table
__device__ __align__(256) float g_A2T[KQ * B];           // [q][b] transposed
__device__ __align__(256) float g_Rg [B * 288];          // per (b,j): 9 R + 3 t'
__device__ __align__(256) float g_P  [B * N2];

__constant__ int c_par[24] = {-1,0,0,0,1,2,3,4,5,6,7,8,9,9,9,12,13,14,16,17,18,19,20,21};

// ---------------------------------------------------------------------------
// K1: build E[v][col] = [posedirs^T | shapedirs^T | v_template | 1], zero pad
// ---------------------------------------------------------------------------
__global__ void k_buildE(const float* __restrict__ posedirs,
                         const float* __restrict__ shapedirs,
                         const float* __restrict__ v_template) {
    int idx = blockIdx.x * blockDim.x + threadIdx.x;
    if (idx >= VP * N1) return;
    int v = idx / N1, col = idx - v * N1;
    float val = 0.f;
    if (v < V) {
        if (col < 621) {
            int p = col / 3, c = col - 3 * p;
            val = posedirs[p * (V * 3) + 3 * v + c];
        } else if (col < 651) {
            int t = col - 621;
            int n = t / 3, c = t - 3 * n;
            val = shapedirs[n * (V * 3) + 3 * v + c];
        } else if (col < 654) {
            val = v_template[v * 3 + (col - 651)];
        } else if (col == 654) {
            val = 1.f;
        }
    }
    g_E[idx] = val;
}

// ---------------------------------------------------------------------------
// K1b: build G[v][row]; row<456: jr[v, row/24]*w[v, row%24]; 456..479: Jreg
// ---------------------------------------------------------------------------
__global__ void k_buildG(const float* __restrict__ jr19,
                         const float* __restrict__ w24,
                         const float* __restrict__ Jreg24) {
    int idx = blockIdx.x * blockDim.x + threadIdx.x;
    if (idx >= VP * M1) return;
    int v = idx / M1, row = idx - v * M1;
    float val = 0.f;
    if (v < V) {
        if (row < 456) {
            int k = row / 24, j = row - 24 * k;
            val = jr19[v * NK + k] * w24[v * NJ + j];
        } else if (row < 480) {
            val = Jreg24[v * NJ + (row - 456)];
        }
    }
    g_G[idx] = val;
}

// ---------------------------------------------------------------------------
// Generic 64x64 tile GEMM:  C[M x N] += over k of A[k][m] * B[k][n]
//   A: [K][lda] (K-major, i.e. A^T), B: [K][ldb], C: [ldc], split-K via z.
//   256 threads, 4x4 per-thread tile, BK=16, reg-prefetch single-buffer smem.
// ---------------------------------------------------------------------------
__global__ void k_gemm64(const float* __restrict__ A, int lda,
                         const float* __restrict__ B, int ldb,
                         float* __restrict__ C, int ldc,
                         int kPerSplit, int cSplitStride) {
    const int split = blockIdx.z;
    const int row0 = blockIdx.y * 64;
    const int col0 = blockIdx.x * 64;
    const float* Ak = A + (size_t)split * kPerSplit * lda;
    const float* Bk = B + (size_t)split * kPerSplit * ldb;
    float* Co = C + (size_t)split * cSplitStride;

    __shared__ __align__(16) float As[16][64];
    __shared__ __align__(16) float Bs[16][64];

    const int tid = threadIdx.x;
    const int kk = tid >> 4;            // 0..15
    const int r4 = (tid & 15) << 2;     // 0..60
    const int tm = (tid >> 4) << 2;     // 0..60
    const int tn = (tid & 15) << 2;     // 0..60

    float acc[4][4] = {};

    const int nIter = kPerSplit >> 4;
    float4 ra = *(const float4*)&Ak[(size_t)kk * lda + row0 + r4];
    float4 rb = *(const float4*)&Bk[(size_t)kk * ldb + col0 + r4];

    for (int it = 0; it < nIter; ++it) {
        __syncthreads();
        *(float4*)&As[kk][r4] = ra;
        *(float4*)&Bs[kk][r4] = rb;
        __syncthreads();
        if (it + 1 < nIter) {
            int kb = (it + 1) * 16 + kk;
            ra = *(const float4*)&Ak[(size_t)kb * lda + row0 + r4];
            rb = *(const float4*)&Bk[(size_t)kb * ldb + col0 + r4];
        }
#pragma unroll
        for (int p = 0; p < 16; ++p) {
            float4 a = *(const float4*)&As[p][tm];
            float4 b = *(const float4*)&Bs[p][tn];
            float av[4] = {a.x, a.y, a.z, a.w};
            float bv[4] = {b.x, b.y, b.z, b.w};
#pragma unroll
            for (int i = 0; i < 4; ++i)
#pragma unroll
                for (int j = 0; j < 4; ++j)
                    acc[i][j] += av[i] * bv[j];
        }
    }

#pragma unroll
    for (int i = 0; i < 4; ++i) {
        float4 o = make_float4(acc[i][0], acc[i][1], acc[i][2], acc[i][3]);
        *(float4*)&Co[(size_t)(row0 + tm + i) * ldc + col0 + tn] = o;
    }
}

// ---------------------------------------------------------------------------
// K-reduce: sum split-K partials, reshuffle into CT[q][m], plus S and JT.
//   CT[q][kj*3+c]:  q=0 -> C0 (col 651+c); q=1..10 -> C1 (col 621+3(q-1)+c);
//                   q=11..217 -> C2 (col 3(q-11)+c); else 0.
// ---------------------------------------------------------------------------
__global__ void k_reduce() {
    int idx = blockIdx.x * blockDim.x + threadIdx.x;
    const int NCT = KQ * N2;
    if (idx < NCT) {
        int q = idx / N2, m = idx - q * N2;
        float val = 0.f;
        if (m < 1368 && q < 218) {
            int kj = m / 3, c = m - 3 * kj;
            int col;
            if (q == 0)        col = 651 + c;
            else if (q <= 10)  col = 621 + (q - 1) * 3 + c;
            else               col = (q - 11) * 3 + c;
            size_t off = (size_t)kj * N1 + col;
#pragma unroll
            for (int s = 0; s < SPLITK; ++s)
                val += g_Cp[(size_t)s * (M1 * N1) + off];
        }
        g_CT[idx] = val;
    } else if (idx < NCT + 456) {
        int kj = idx - NCT;
        float val = 0.f;
#pragma unroll
        for (int s = 0; s < SPLITK; ++s)
            val += g_Cp[(size_t)s * (M1 * N1) + (size_t)kj * N1 + 654];
        g_S[kj] = val;
    } else if (idx < NCT + 456 + 24 * 33) {
        int t2 = idx - NCT - 456;
        int j = t2 / 33, t = t2 - 33 * j;
        float val = 0.f;
#pragma unroll
        for (int s = 0; s < SPLITK; ++s)
            val += g_Cp[(size_t)s * (M1 * N1) + (size_t)(456 + j) * N1 + 621 + t];
        g_JT[t2] = val;
    }
}

// ---------------------------------------------------------------------------
// K3a: per-body (one warp / body): Rodrigues, J, A2T column, kinematic chain,
//      global R + adjusted translation t' = t_glob - Rglob @ J.
// ---------------------------------------------------------------------------
__global__ void k_prep(const float* __restrict__ beta,
                       const float* __restrict__ theta) {
    const int b = blockIdx.x;
    const int lane = threadIdx.x;       // 32 threads

    __shared__ float Rsm[24][9];
    __shared__ float Jm[24][3];
    __shared__ float Ag[24][12];        // rows r<3 of 4x4 global xform
    __shared__ float bet[10];

    if (lane < 10) bet[lane] = beta[b * NB + lane];
    __syncwarp();

    if (lane < 24) {
        float tx = theta[b * 72 + lane * 3 + 0];
        float ty = theta[b * 72 + lane * 3 + 1];
        float tz = theta[b * 72 + lane * 3 + 2];
        float ax = tx + 1e-8f, ay = ty + 1e-8f, az = tz + 1e-8f;
        float angle = sqrtf(ax * ax + ay * ay + az * az);
        float half = 0.5f * angle;
        float s = sinf(half), cw = cosf(half);
        float vx = tx / angle * s, vy = ty / angle * s, vz = tz / angle * s;
        float qn = sqrtf(cw * cw + vx * vx + vy * vy + vz * vz);
        float w = cw / qn, x = vx / qn, y = vy / qn, z = vz / qn;
        Rsm[lane][0] = 1.f - 2.f * (y * y + z * z);
        Rsm[lane][1] = 2.f * (x * y - w * z);
        Rsm[lane][2] = 2.f * (x * z + w * y);
        Rsm[lane][3] = 2.f * (x * y + w * z);
        Rsm[lane][4] = 1.f - 2.f * (x * x + z * z);
        Rsm[lane][5] = 2.f * (y * z - w * x);
        Rsm[lane][6] = 2.f * (x * z - w * y);
        Rsm[lane][7] = 2.f * (y * z + w * x);
        Rsm[lane][8] = 1.f - 2.f * (x * x + y * y);
        // J[b,j,c] = JT0 + sum_n beta[n] * JT1
#pragma unroll
        for (int c = 0; c < 3; ++c) {
            float val = g_JT[lane * 33 + 30 + c];
#pragma unroll
            for (int n = 0; n < 10; ++n)
                val += bet[n] * g_JT[lane * 33 + n * 3 + c];
            Jm[lane][c] = val;
        }
    }
    __syncwarp();

    // A2T column: [1 | beta(10) | pose_feature(207) | zero pad]
    for (int q = lane; q < KQ; q += 32) {
        float val;
        if (q == 0) val = 1.f;
        else if (q <= 10) val = bet[q - 1];
        else if (q < 218) {
            int p = q - 11;
            int i = p / 9 + 1, e = p - 9 * (p / 9);
            val = Rsm[i][e] - ((e == 0 || e == 4 || e == 8) ? 1.f : 0.f);
        } else val = 0.f;
        g_A2T[q * B + b] = val;
    }

    // Kinematic chain (parents precede children in index order)
    const int r = lane >> 2, cc = lane & 3;
    for (int i = 0; i < 24; ++i) {
        if (lane < 12) {
            float val;
            if (i == 0) {
                // root_R = Rs[0] @ diag(1,-1,-1); t = J[0]
                val = (cc < 3) ? Rsm[0][r * 3 + cc] * (cc == 0 ? 1.f : -1.f)
                               : Jm[0][r];
            } else {
                int par = c_par[i];
                float l0, l1, l2;
                if (cc < 3) {
                    l0 = Rsm[i][0 * 3 + cc];
                    l1 = Rsm[i][1 * 3 + cc];
                    l2 = Rsm[i][2 * 3 + cc];
                } else {
                    l0 = Jm[i][0] - Jm[par][0];
                    l1 = Jm[i][1] - Jm[par][1];
                    l2 = Jm[i][2] - Jm[par][2];
                }
                val = Ag[par][r * 4 + 0] * l0 + Ag[par][r * 4 + 1] * l1 +
                      Ag[par][r * 4 + 2] * l2;
                if (cc == 3) val += Ag[par][r * 4 + 3];
            }
            Ag[i][r * 4 + cc] = val;
        }
        __syncwarp();
    }

    // Emit [R(9), t'(3)] per joint; t' = t_glob - Rglob @ J
    for (int idx = lane; idx < 288; idx += 32) {
        int j = idx / 12, e = idx - 12 * j;
        float out;
        if (e < 9) {
            int rr = e / 3, c = e - 3 * rr;
            out = Ag[j][rr * 4 + c];
        } else {
            int rr = e - 9;
            out = Ag[j][rr * 4 + 3] -
                  (Ag[j][rr * 4 + 0] * Jm[j][0] + Ag[j][rr * 4 + 1] * Jm[j][1] +
                   Ag[j][rr * 4 + 2] * Jm[j][2]);
        }
        g_Rg[b * 288 + idx] = out;
    }
}

// ---------------------------------------------------------------------------
// K3c: joints[b,k,r] = trans[r] + sum_j ( R[b,j][r,:]·P[b,k,j,:] + t'[b,j,r]·S[k,j] )
// ---------------------------------------------------------------------------
__global__ void k_joints(const float* __restrict__ trans,
                         float* __restrict__ out) {
    const int b = blockIdx.x;
    const int tid = threadIdx.x;        // 64 threads
    __shared__ float sA[288];
    __shared__ float sS[456];
    for (int i = tid; i < 288; i += 64) sA[i] = g_Rg[b * 288 + i];
    for (int i = tid; i < 456; i += 64) sS[i] = g_S[i];
    __syncthreads();
    if (tid < 57) {
        int k = tid / 3, r = tid - 3 * k;
        float acc = trans[b * 3 + r];
        const float* Pb = &g_P[(size_t)b * N2];
#pragma unroll
        for (int j = 0; j < 24; ++j) {
            const float* M = &sA[j * 12];
            int m = (k * 24 + j) * 3;
            float p0 = Pb[m + 0], p1 = Pb[m + 1], p2 = Pb[m + 2];
            acc += M[r * 3 + 0] * p0 + M[r * 3 + 1] * p1 + M[r * 3 + 2] * p2 +
                   M[9 + r] * sS[k * 24 + j];
        }
        out[b * 57 + tid] = acc;
    }
}

} // namespace smpl

extern "C" void kernel_launch(void* const* d_in, const int* in_sizes, int n_in,
                              void* d_out, int out_size) {
    using namespace smpl;
    const float* beta       = (const float*)d_in[0];
    const float* theta      = (const float*)d_in[1];
    const float* trans      = (const float*)d_in[2];
    const float* v_template = (const float*)d_in[3];
    const float* shapedirs  = (const float*)d_in[4];
    const float* J_reg      = (const float*)d_in[5];
    const float* posedirs   = (const float*)d_in[6];
    const float* joint_reg  = (const float*)d_in[7];
    const float* weights    = (const float*)d_in[8];
    float* out = (float*)d_out;

    float *pE, *pG, *pCp, *pCT, *pA2T, *pP;
    cudaGetSymbolAddress((void**)&pE,   g_E);
    cudaGetSymbolAddress((void**)&pG,   g_G);
    cudaGetSymbolAddress((void**)&pCp,  g_Cp);
    cudaGetSymbolAddress((void**)&pCT,  g_CT);
    cudaGetSymbolAddress((void**)&pA2T, g_A2T);
    cudaGetSymbolAddress((void**)&pP,   g_P);

    // 1) Build E (transposed direction matrix) and G (regressor products)
    {
        int n = VP * N1;
        k_buildE<<<(n + 255) / 256, 256>>>(posedirs, shapedirs, v_template);
    }
    {
        int n = VP * M1;
        k_buildG<<<(n + 255) / 256, 256>>>(joint_reg, weights, J_reg);
    }

    // 2) GEMM1: Cpart[s] = G^T @ E  (split-K = 8)
    {
        dim3 grid(N1 / 64, M1 / 64, SPLITK);   // 11 x 8 x 8
        k_gemm64<<<grid, 256>>>(pG, M1, pE, N1, pCp, N1, VP / SPLITK, M1 * N1);
    }

    // 3) Reduce partials -> CT / S / JT
    {
        int n = KQ * N2 + 456 + 24 * 33;
        k_reduce<<<(n + 255) / 256, 256>>>();
    }

    // 4) Per-body prep: Rodrigues, J, chain, pose-feature row (A2T column)
    k_prep<<<B, 32>>>(beta, theta);

    // 5) GEMM2: P = A2 @ CT
    {
        dim3 grid(N2 / 64, B / 64, 1);          // 22 x 16
        k_gemm64<<<grid, 256>>>(pA2T, B, pCT, N2, pP, N2, KQ, 0);
    }

    // 6) Joints epilogue
    k_joints<<<B, 64>>>(trans, out);
}